// round 13
// baseline (speedup 1.0000x reference)
#include <cuda_runtime.h>
#include <cstdint>

#define Bn 128
#define Tn 512
#define Dn 128
#define NCOL (Bn * Tn)                  // 65536 columns
#define COPY_N4 (Bn * Tn * Tn / 4)      // 8,388,608 float4
#define NCHUNK 4                        // row chunks per column scan
#define CHUNK 128

// K1 roles
#define SCAN_BLOCKS 1024                // 128 b x 2 colblocks x 4 chunks
#define RAMP_BLOCKS 128
#define CPA_BLOCKS 2048
#define K1_BLOCKS (SCAN_BLOCKS + RAMP_BLOCKS + CPA_BLOCKS)
#define CPA_N4 4823040                  // ~57.5% of copy (K1 got lighter)

// K2 roles: spmm 4 columns per warp (R12).
#define SPMM_BLOCKS (NCOL / 32)         // 2048: 8 warps x 4 cols = 32 cols/blk
#define CPB_BLOCKS 2048
#define K2_BLOCKS (SPMM_BLOCKS + CPB_BLOCKS)

// Per-(column, chunk) support range, interleaved for 8B vector merge loads.
__device__ short g_s[NCOL * NCHUNK];
__device__ short g_e[NCOL * NCHUNK];

// int32 vs int64 auto-detect: values >= 1, so word[1]==0 <=> int64 buffer.
__device__ __forceinline__ int load_len(const int* __restrict__ raw, int b) {
    int stride = (raw[1] == 0) ? 2 : 1;
    return __ldg(raw + b * stride);
}

// Sparse-aware grid-stride copy (R6-proven): read SeqtoBlur only inside the
// len x alen corner; write everything (clears 0xAA poison).
__device__ __forceinline__ void copy_sparse(
    const float4* __restrict__ s4, float4* __restrict__ d4,
    const int* __restrict__ len_raw, const int* __restrict__ alen_raw,
    int base, int end, int tid_global, int nthreads)
{
    const float4 z = make_float4(0.f, 0.f, 0.f, 0.f);
    int i = base + tid_global * 4;
    int stride = nthreads * 4;
    for (; i + 3 < end; i += stride) {
        float4 v[4];
#pragma unroll
        for (int k = 0; k < 4; ++k) {
            int idx = i + k;
            int b = idx >> 16;
            int r = (idx >> 7) & (Tn - 1);
            int c4 = idx & 127;
            bool rd = (r < load_len(len_raw, b)) &&
                      (c4 * 4 < load_len(alen_raw, b));
            v[k] = rd ? __ldg(s4 + idx) : z;
        }
#pragma unroll
        for (int k = 0; k < 4; ++k) d4[i + k] = v[k];
    }
    for (; i < end; ++i) {
        int b = i >> 16;
        int r = (i >> 7) & (Tn - 1);
        int c4 = i & 127;
        bool rd = (r < load_len(len_raw, b)) && (c4 * 4 < load_len(alen_raw, b));
        d4[i] = rd ? __ldg(s4 + i) : z;
    }
}

// ---------------------------------------------------------------------------
// K1: windowed column-support scan + ramps + copy slice A.
// Support window (all branches): support(col i) ⊆ [i, len - alen + i].
// A warp covering cols [c0, c0+32) scans rows [c0, len - alen + c0 + 32).
// ---------------------------------------------------------------------------
__global__ void __launch_bounds__(256) k1(
    const float* __restrict__ seqtoblur, float* __restrict__ out_stb,
    const float* __restrict__ bm,
    const int* __restrict__ len_raw, const int* __restrict__ alen_raw,
    float* __restrict__ R, float* __restrict__ aR,
    float* __restrict__ alen_out, int alen_mode)
{
    int blk = blockIdx.x;
    int tid = threadIdx.x;

    if (blk < SCAN_BLOCKS) {
        // blk = (b * 2 + colblk) * NCHUNK + c
        int c = blk & (NCHUNK - 1);
        int bc = blk >> 2;
        int b = bc >> 1;
        int i = ((bc & 1) << 8) + tid;          // column; lanes adjacent
        int col = b * Tn + i;
        int len  = load_len(len_raw, b);
        int alen = load_len(alen_raw, b);
        int t0 = c * CHUNK;
        int warp_c0 = ((bc & 1) << 8) + (tid & ~31);   // warp's first column
        // Warp-uniform scan window intersected with this chunk.
        int lo = max(t0, warp_c0);
        int hi = min(min(t0 + CHUNK, len), len - alen + warp_c0 + 32);
        int s = Tn, e = -1;
        // len<=2 => eye case handled in spmm; cols >= alen are all zero.
        if (len > 2 && warp_c0 < alen && hi > lo) {
            const float* colp = bm + (size_t)b * Tn * Tn + i;
#pragma unroll 4
            for (int t = lo; t < hi; ++t) {
                float v = __ldg(colp + (size_t)t * Tn);
                if (v != 0.0f) { s = (t < s) ? t : s; e = t; }
            }
        }
        g_s[col * NCHUNK + c] = (short)(e >= 0 ? s : Tn);
        g_e[col * NCHUNK + c] = (short)e;
        return;
    }

    if (blk < SCAN_BLOCKS + RAMP_BLOCKS) {
        int b = blk - SCAN_BLOCKS;
        int l  = load_len(len_raw, b);
        int al = load_len(alen_raw, b);
        float invl  = 1.0f / fmaxf((float)l,  1.0f);
        float inval = 1.0f / fmaxf((float)al, 1.0f);
#pragma unroll
        for (int t = tid; t < Tn; t += 256) {
            R[b * Tn + t]  = (t < l)  ? (float)(t + 1) * invl  : 0.0f;
            aR[b * Tn + t] = (t < al) ? (float)(t + 1) * inval : 0.0f;
        }
        if (tid == 0) {
            if (alen_mode == 1)      alen_out[b] = (float)al;
            else if (alen_mode == 2) ((long long*)alen_out)[b] = (long long)al;
        }
        return;
    }

    // Copy slice A.
    {
        int cblk = blk - (SCAN_BLOCKS + RAMP_BLOCKS);
        copy_sparse((const float4*)seqtoblur, (float4*)out_stb,
                    len_raw, alen_raw,
                    0, CPA_N4, cblk * 256 + tid, CPA_BLOCKS * 256);
    }
}

// ---------------------------------------------------------------------------
// K2: sparse gather — one warp per 4 ADJACENT columns (vector w loads, shared
// seq-row loads) + copy slice B.  (R12 verbatim)
// ---------------------------------------------------------------------------
__global__ void __launch_bounds__(256) k2(
    const float* __restrict__ seq,
    const float* __restrict__ seqtoblur, float* __restrict__ out_stb,
    const float* __restrict__ bm,
    const int* __restrict__ len_raw, const int* __restrict__ alen_raw,
    float* __restrict__ out_avged)
{
    int blk = blockIdx.x;
    int tid = threadIdx.x;

    if (blk < SPMM_BLOCKS) {
        int warp = tid >> 5;
        int lane = tid & 31;
        int col4 = (blk * 8 + warp) * 4;       // first of 4 adjacent columns
        int b = col4 >> 9;
        int i = col4 & (Tn - 1);
        int len = load_len(len_raw, b);

        const float4* seqb = (const float4*)(seq + (size_t)b * Tn * Dn) + lane;
        float* outb = out_avged + ((size_t)b * Tn + i) * Dn;

        if (len <= 2) {
            // BlurMat = eye(512): avged_seq rows = seq rows.
#pragma unroll
            for (int c = 0; c < 4; ++c)
                ((float4*)(outb + (size_t)c * Dn))[lane] =
                    __ldg(seqb + (size_t)(i + c) * (Dn / 4));
            return;
        }

        // Union range over the 4 columns.
        int s = Tn, e = -1;
#pragma unroll
        for (int c = 0; c < 4; ++c) {
            const short4 sv = *(const short4*)(g_s + (col4 + c) * NCHUNK);
            const short4 ev = *(const short4*)(g_e + (col4 + c) * NCHUNK);
            int sc = min(min((int)sv.x, (int)sv.y), min((int)sv.z, (int)sv.w));
            int ec = max(max((int)ev.x, (int)ev.y), max((int)ev.z, (int)ev.w));
            s = min(s, sc);
            e = max(e, ec);
        }

        const float* bmb = bm + (size_t)b * Tn * Tn + i;   // 16B-aligned (i%4==0)
        float4 acc0 = {0.f,0.f,0.f,0.f}, acc1 = {0.f,0.f,0.f,0.f};
        float4 acc2 = {0.f,0.f,0.f,0.f}, acc3 = {0.f,0.f,0.f,0.f};
        for (int t = s; t <= e; ++t) {
            float4 w = __ldg((const float4*)(bmb + (size_t)t * Tn)); // 4 cols' weights
            float4 v = __ldg(seqb + (size_t)t * (Dn / 4));           // shared row
            acc0.x = fmaf(w.x, v.x, acc0.x); acc0.y = fmaf(w.x, v.y, acc0.y);
            acc0.z = fmaf(w.x, v.z, acc0.z); acc0.w = fmaf(w.x, v.w, acc0.w);
            acc1.x = fmaf(w.y, v.x, acc1.x); acc1.y = fmaf(w.y, v.y, acc1.y);
            acc1.z = fmaf(w.y, v.z, acc1.z); acc1.w = fmaf(w.y, v.w, acc1.w);
            acc2.x = fmaf(w.z, v.x, acc2.x); acc2.y = fmaf(w.z, v.y, acc2.y);
            acc2.z = fmaf(w.z, v.z, acc2.z); acc2.w = fmaf(w.z, v.w, acc2.w);
            acc3.x = fmaf(w.w, v.x, acc3.x); acc3.y = fmaf(w.w, v.y, acc3.y);
            acc3.z = fmaf(w.w, v.z, acc3.z); acc3.w = fmaf(w.w, v.w, acc3.w);
        }
        // Full writes clear 0xAA poison + handle k==5 all-zero / empty ranges.
        ((float4*)(outb + 0 * Dn))[lane] = acc0;
        ((float4*)(outb + 1 * Dn))[lane] = acc1;
        ((float4*)(outb + 2 * Dn))[lane] = acc2;
        ((float4*)(outb + 3 * Dn))[lane] = acc3;
        return;
    }

    // Copy slice B.
    {
        int cblk = blk - SPMM_BLOCKS;
        copy_sparse((const float4*)seqtoblur, (float4*)out_stb,
                    len_raw, alen_raw,
                    CPA_N4, COPY_N4, cblk * 256 + tid, CPB_BLOCKS * 256);
    }
}

extern "C" void kernel_launch(void* const* d_in, const int* in_sizes, int n_in,
                              void* d_out, int out_size) {
    const float* seq       = (const float*)d_in[0];
    const int*   len_raw   = (const int*)d_in[1];
    const float* seqtoblur = (const float*)d_in[2];
    const float* blurmat   = (const float*)d_in[3];
    const int*   alen_raw  = (const int*)d_in[4];

    float* out = (float*)d_out;

    const size_t OFF_AVG  = (size_t)Bn * Tn * Tn;             // 33,554,432
    const size_t OFF_R    = OFF_AVG + (size_t)Bn * Tn * Dn;   // 41,943,040
    const size_t OFF_AR   = OFF_R + (size_t)Bn * Tn;          // 42,008,576
    const size_t OFF_ALEN = OFF_AR + (size_t)Bn * Tn;         // 42,074,112

    long long rem = (long long)out_size - (long long)OFF_ALEN;
    int alen_mode = 0;
    if (rem == Bn) alen_mode = 1;          // avged_len as float32
    else if (rem == 2 * Bn) alen_mode = 2; // avged_len as raw int64

    k1<<<K1_BLOCKS, 256>>>(seqtoblur, out, blurmat,
                           len_raw, alen_raw,
                           out + OFF_R, out + OFF_AR,
                           out + OFF_ALEN, alen_mode);

    k2<<<K2_BLOCKS, 256>>>(seq, seqtoblur, out, blurmat,
                           len_raw, alen_raw, out + OFF_AVG);
}

// round 14
// speedup vs baseline: 1.0886x; 1.0886x over previous
#include <cuda_runtime.h>
#include <cstdint>

#define Bn 128
#define Tn 512
#define Dn 128
#define NCOL (Bn * Tn)                  // 65536 columns
#define COPY_N4 (Bn * Tn * Tn / 4)      // 8,388,608 float4
#define NCHUNK 4                        // window quarters per column scan

// K1 roles (R12 sizes)
#define SCAN_BLOCKS 1024                // 128 b x 2 colblocks x 4 chunks
#define RAMP_BLOCKS 128
#define CPA_BLOCKS 2048
#define K1_BLOCKS (SCAN_BLOCKS + RAMP_BLOCKS + CPA_BLOCKS)
#define CPA_N4 4718592                  // ~56% of copy (R12 balance)

// K2 roles: spmm 4 columns per warp (R12).
#define SPMM_BLOCKS (NCOL / 32)         // 2048: 8 warps x 4 cols = 32 cols/blk
#define CPB_BLOCKS 2048
#define K2_BLOCKS (SPMM_BLOCKS + CPB_BLOCKS)

// Per-(column, chunk) support range, interleaved for 8B vector merge loads.
__device__ short g_s[NCOL * NCHUNK];
__device__ short g_e[NCOL * NCHUNK];

// int32 vs int64 auto-detect: values >= 1, so word[1]==0 <=> int64 buffer.
__device__ __forceinline__ int load_len(const int* __restrict__ raw, int b) {
    int stride = (raw[1] == 0) ? 2 : 1;
    return __ldg(raw + b * stride);
}

// Sparse-aware grid-stride copy (R6-proven): read SeqtoBlur only inside the
// len x alen corner; write everything (clears 0xAA poison).
__device__ __forceinline__ void copy_sparse(
    const float4* __restrict__ s4, float4* __restrict__ d4,
    const int* __restrict__ len_raw, const int* __restrict__ alen_raw,
    int base, int end, int tid_global, int nthreads)
{
    const float4 z = make_float4(0.f, 0.f, 0.f, 0.f);
    int i = base + tid_global * 4;
    int stride = nthreads * 4;
    for (; i + 3 < end; i += stride) {
        float4 v[4];
#pragma unroll
        for (int k = 0; k < 4; ++k) {
            int idx = i + k;
            int b = idx >> 16;
            int r = (idx >> 7) & (Tn - 1);
            int c4 = idx & 127;
            bool rd = (r < load_len(len_raw, b)) &&
                      (c4 * 4 < load_len(alen_raw, b));
            v[k] = rd ? __ldg(s4 + idx) : z;
        }
#pragma unroll
        for (int k = 0; k < 4; ++k) d4[i + k] = v[k];
    }
    for (; i < end; ++i) {
        int b = i >> 16;
        int r = (i >> 7) & (Tn - 1);
        int c4 = i & 127;
        bool rd = (r < load_len(len_raw, b)) && (c4 * 4 < load_len(alen_raw, b));
        d4[i] = rd ? __ldg(s4 + i) : z;
    }
}

// ---------------------------------------------------------------------------
// K1: window-balanced column-support scan + ramps + copy slice A.
// Support window (verified in R13): support(col i) ⊆ [i, len - alen + i].
// Warp window = [warp_c0, min(len, len - alen + warp_c0 + 32)); chunk block c
// scans the c-th quarter of the window -> equal work per chunk.
// ---------------------------------------------------------------------------
__global__ void __launch_bounds__(256) k1(
    const float* __restrict__ seqtoblur, float* __restrict__ out_stb,
    const float* __restrict__ bm,
    const int* __restrict__ len_raw, const int* __restrict__ alen_raw,
    float* __restrict__ R, float* __restrict__ aR,
    float* __restrict__ alen_out, int alen_mode)
{
    int blk = blockIdx.x;
    int tid = threadIdx.x;

    if (blk < SCAN_BLOCKS) {
        // blk = (b * 2 + colblk) * NCHUNK + c
        int c = blk & (NCHUNK - 1);
        int bc = blk >> 2;
        int b = bc >> 1;
        int i = ((bc & 1) << 8) + tid;          // column; lanes adjacent
        int col = b * Tn + i;
        int len  = load_len(len_raw, b);
        int alen = load_len(alen_raw, b);
        int warp_c0 = ((bc & 1) << 8) + (tid & ~31);   // warp's first column
        // Warp-uniform window.
        int lo = warp_c0;
        int hi = min(len, len - alen + warp_c0 + 32);
        int s = Tn, e = -1;
        // len<=2 => eye case handled in spmm; cols >= alen are all zero.
        if (len > 2 && warp_c0 < alen && hi > lo) {
            int span = hi - lo;
            int t_lo = lo + (c * span) / NCHUNK;
            int t_hi = lo + ((c + 1) * span) / NCHUNK;
            const float* colp = bm + (size_t)b * Tn * Tn + i;
#pragma unroll 4
            for (int t = t_lo; t < t_hi; ++t) {
                float v = __ldg(colp + (size_t)t * Tn);
                if (v != 0.0f) { s = (t < s) ? t : s; e = t; }
            }
        }
        g_s[col * NCHUNK + c] = (short)(e >= 0 ? s : Tn);
        g_e[col * NCHUNK + c] = (short)e;
        return;
    }

    if (blk < SCAN_BLOCKS + RAMP_BLOCKS) {
        int b = blk - SCAN_BLOCKS;
        int l  = load_len(len_raw, b);
        int al = load_len(alen_raw, b);
        float invl  = 1.0f / fmaxf((float)l,  1.0f);
        float inval = 1.0f / fmaxf((float)al, 1.0f);
#pragma unroll
        for (int t = tid; t < Tn; t += 256) {
            R[b * Tn + t]  = (t < l)  ? (float)(t + 1) * invl  : 0.0f;
            aR[b * Tn + t] = (t < al) ? (float)(t + 1) * inval : 0.0f;
        }
        if (tid == 0) {
            if (alen_mode == 1)      alen_out[b] = (float)al;
            else if (alen_mode == 2) ((long long*)alen_out)[b] = (long long)al;
        }
        return;
    }

    // Copy slice A.
    {
        int cblk = blk - (SCAN_BLOCKS + RAMP_BLOCKS);
        copy_sparse((const float4*)seqtoblur, (float4*)out_stb,
                    len_raw, alen_raw,
                    0, CPA_N4, cblk * 256 + tid, CPA_BLOCKS * 256);
    }
}

// ---------------------------------------------------------------------------
// K2: sparse gather — one warp per 4 ADJACENT columns (vector w loads, shared
// seq-row loads) + copy slice B.  (R12 verbatim)
// ---------------------------------------------------------------------------
__global__ void __launch_bounds__(256) k2(
    const float* __restrict__ seq,
    const float* __restrict__ seqtoblur, float* __restrict__ out_stb,
    const float* __restrict__ bm,
    const int* __restrict__ len_raw, const int* __restrict__ alen_raw,
    float* __restrict__ out_avged)
{
    int blk = blockIdx.x;
    int tid = threadIdx.x;

    if (blk < SPMM_BLOCKS) {
        int warp = tid >> 5;
        int lane = tid & 31;
        int col4 = (blk * 8 + warp) * 4;       // first of 4 adjacent columns
        int b = col4 >> 9;
        int i = col4 & (Tn - 1);
        int len = load_len(len_raw, b);

        const float4* seqb = (const float4*)(seq + (size_t)b * Tn * Dn) + lane;
        float* outb = out_avged + ((size_t)b * Tn + i) * Dn;

        if (len <= 2) {
            // BlurMat = eye(512): avged_seq rows = seq rows.
#pragma unroll
            for (int c = 0; c < 4; ++c)
                ((float4*)(outb + (size_t)c * Dn))[lane] =
                    __ldg(seqb + (size_t)(i + c) * (Dn / 4));
            return;
        }

        // Union range over the 4 columns.
        int s = Tn, e = -1;
#pragma unroll
        for (int c = 0; c < 4; ++c) {
            const short4 sv = *(const short4*)(g_s + (col4 + c) * NCHUNK);
            const short4 ev = *(const short4*)(g_e + (col4 + c) * NCHUNK);
            int sc = min(min((int)sv.x, (int)sv.y), min((int)sv.z, (int)sv.w));
            int ec = max(max((int)ev.x, (int)ev.y), max((int)ev.z, (int)ev.w));
            s = min(s, sc);
            e = max(e, ec);
        }

        const float* bmb = bm + (size_t)b * Tn * Tn + i;   // 16B-aligned (i%4==0)
        float4 acc0 = {0.f,0.f,0.f,0.f}, acc1 = {0.f,0.f,0.f,0.f};
        float4 acc2 = {0.f,0.f,0.f,0.f}, acc3 = {0.f,0.f,0.f,0.f};
        for (int t = s; t <= e; ++t) {
            float4 w = __ldg((const float4*)(bmb + (size_t)t * Tn)); // 4 cols' weights
            float4 v = __ldg(seqb + (size_t)t * (Dn / 4));           // shared row
            acc0.x = fmaf(w.x, v.x, acc0.x); acc0.y = fmaf(w.x, v.y, acc0.y);
            acc0.z = fmaf(w.x, v.z, acc0.z); acc0.w = fmaf(w.x, v.w, acc0.w);
            acc1.x = fmaf(w.y, v.x, acc1.x); acc1.y = fmaf(w.y, v.y, acc1.y);
            acc1.z = fmaf(w.y, v.z, acc1.z); acc1.w = fmaf(w.y, v.w, acc1.w);
            acc2.x = fmaf(w.z, v.x, acc2.x); acc2.y = fmaf(w.z, v.y, acc2.y);
            acc2.z = fmaf(w.z, v.z, acc2.z); acc2.w = fmaf(w.z, v.w, acc2.w);
            acc3.x = fmaf(w.w, v.x, acc3.x); acc3.y = fmaf(w.w, v.y, acc3.y);
            acc3.z = fmaf(w.w, v.z, acc3.z); acc3.w = fmaf(w.w, v.w, acc3.w);
        }
        // Full writes clear 0xAA poison + handle k==5 all-zero / empty ranges.
        ((float4*)(outb + 0 * Dn))[lane] = acc0;
        ((float4*)(outb + 1 * Dn))[lane] = acc1;
        ((float4*)(outb + 2 * Dn))[lane] = acc2;
        ((float4*)(outb + 3 * Dn))[lane] = acc3;
        return;
    }

    // Copy slice B.
    {
        int cblk = blk - SPMM_BLOCKS;
        copy_sparse((const float4*)seqtoblur, (float4*)out_stb,
                    len_raw, alen_raw,
                    CPA_N4, COPY_N4, cblk * 256 + tid, CPB_BLOCKS * 256);
    }
}

extern "C" void kernel_launch(void* const* d_in, const int* in_sizes, int n_in,
                              void* d_out, int out_size) {
    const float* seq       = (const float*)d_in[0];
    const int*   len_raw   = (const int*)d_in[1];
    const float* seqtoblur = (const float*)d_in[2];
    const float* blurmat   = (const float*)d_in[3];
    const int*   alen_raw  = (const int*)d_in[4];

    float* out = (float*)d_out;

    const size_t OFF_AVG  = (size_t)Bn * Tn * Tn;             // 33,554,432
    const size_t OFF_R    = OFF_AVG + (size_t)Bn * Tn * Dn;   // 41,943,040
    const size_t OFF_AR   = OFF_R + (size_t)Bn * Tn;          // 42,008,576
    const size_t OFF_ALEN = OFF_AR + (size_t)Bn * Tn;         // 42,074,112

    long long rem = (long long)out_size - (long long)OFF_ALEN;
    int alen_mode = 0;
    if (rem == Bn) alen_mode = 1;          // avged_len as float32
    else if (rem == 2 * Bn) alen_mode = 2; // avged_len as raw int64

    k1<<<K1_BLOCKS, 256>>>(seqtoblur, out, blurmat,
                           len_raw, alen_raw,
                           out + OFF_R, out + OFF_AR,
                           out + OFF_ALEN, alen_mode);

    k2<<<K2_BLOCKS, 256>>>(seq, seqtoblur, out, blurmat,
                           len_raw, alen_raw, out + OFF_AVG);
}